// round 5
// baseline (speedup 1.0000x reference)
#include <cuda_runtime.h>
#include <stdint.h>

// ============================================================================
//   msg[E,320] = [x[row] | x[col] | ea];  h = relu(msg@W1+b1);  o = h@W2
//   out[n] = sum_{e:row=n} o_e + deg[n]*b2
// Plain-sm_100 implementation: mma.sync.m16n8k8 tf32 (no tcgen05 — harness
// compiles at compute_100 where tcgen05 is unavailable).
// ============================================================================
#define E_TOTAL   640000
#define NN_NODES  100000
#define OUT_ELEMS (NN_NODES * 128)
#define TILE_E    128
#define N_TILES   (E_TOTAL / TILE_E)   // 5000
#define NCHUNK1   10                   // K1 = 320 = 10*32
#define NCHUNK2   8                    // K2 = 256 = 8*32
#define GRID_MAIN 148

// SMEM layout (bytes), total = 232448 (227 KB max dynamic)
#define SOFF_ROWS 0        // 128 int
#define SOFF_COLS 512      // 128 int
#define SOFF_B1   1024     // 256 float
#define ABUF_OFF  3072     // 2 x 16384  (gathered msg chunk, tf32, swizzled)
#define WBUF_OFF  35840    // 2 x 32768  (W1 chunk dbuf; reused 2x16384 for W2)
#define H_OFF     101376   // 131072    (h[128,256] tf32, swizzled)
#define SMEM_TOTAL 232448

// ============================================================================
// Device scratch (allocation-free)
// ============================================================================
__device__ float g_W1t[NCHUNK1 * 8192];  // per-chunk SMEM images, pre-swizzled
__device__ float g_W2t[NCHUNK2 * 4096];
__device__ int   g_deg[NN_NODES];
__device__ int   g_is64;

// ============================================================================
// Helpers
// ============================================================================
__device__ __forceinline__ uint32_t f2tf32(float f) {
    uint32_t r;
    asm("cvt.rna.tf32.f32 %0, %1;" : "=r"(r) : "f"(f));
    return r;
}
__device__ __forceinline__ void mma8(float* d, const uint32_t* a, const uint32_t* b) {
    asm volatile(
        "mma.sync.aligned.m16n8k8.row.col.f32.tf32.tf32.f32 "
        "{%0,%1,%2,%3}, {%4,%5,%6,%7}, {%8,%9}, {%0,%1,%2,%3};"
        : "+f"(d[0]), "+f"(d[1]), "+f"(d[2]), "+f"(d[3])
        : "r"(a[0]), "r"(a[1]), "r"(a[2]), "r"(a[3]), "r"(b[0]), "r"(b[1]));
}
__device__ __forceinline__ void red2(float* p, float v0, float v1) {
    asm volatile("red.global.add.v2.f32 [%0], {%1, %2};"
                 :: "l"(p), "f"(v0), "f"(v1) : "memory");
}
// W-chunk in-row position permutation: (k, k+4) adjacent -> one LDS.64 per B frag
__device__ __host__ __forceinline__ int wpos(int kk) {
    return ((kk >> 3) << 3) + ((kk & 3) << 1) + ((kk >> 2) & 1);
}

// ============================================================================
// Aux kernels
// ============================================================================
// edge_index dtype probe: int64 values <2^31 => every odd 32-bit word is 0.
__global__ void detect_kernel(const void* ei) {
    const unsigned* w = (const unsigned*)ei;
    int is64 = 1;
    for (int i = 0; i < 64; i++)
        if (w[2 * i + 1] != 0) { is64 = 0; break; }
    g_is64 = is64;
}

__global__ void zero_kernel(float* __restrict__ out) {
    int i = blockIdx.x * 256 + threadIdx.x;
    if (i < OUT_ELEMS) out[i] = 0.0f;
    if (i < NN_NODES) g_deg[i] = 0;
}

// Build pre-swizzled, pre-permuted, tf32-converted weight chunk images.
// Chunk row n holds k in [32c,32c+32) at float index n*32 + (wpos(k&31) ^ 4*(n&7)).
__global__ void prep_kernel(const float* __restrict__ W1, const float* __restrict__ W2) {
    int i = blockIdx.x * 256 + threadIdx.x;
    if (i < 320 * 256) {
        int k = i >> 8, n = i & 255;
        int idx = n * 32 + (wpos(k & 31) ^ ((n & 7) << 2));
        g_W1t[(k >> 5) * 8192 + idx] = __uint_as_float(f2tf32(W1[i]));
    } else if (i < 320 * 256 + 256 * 128) {
        int j = i - 320 * 256;
        int k = j >> 7, n = j & 127;
        int idx = n * 32 + (wpos(k & 31) ^ ((n & 7) << 2));
        g_W2t[(k >> 5) * 4096 + idx] = __uint_as_float(f2tf32(W2[j]));
    }
}

__global__ void deg_kernel(const void* __restrict__ ei) {
    int e = blockIdx.x * 256 + threadIdx.x;
    if (e < E_TOTAL) {
        int r = g_is64 ? (int)((const long long*)ei)[e] : ((const int*)ei)[e];
        atomicAdd(&g_deg[r], 1);
    }
}

__global__ void bias_kernel(float* __restrict__ out, const float* __restrict__ b2) {
    int i = blockIdx.x * 256 + threadIdx.x;
    if (i < OUT_ELEMS) out[i] += (float)g_deg[i >> 7] * b2[i & 127];
}

// ============================================================================
// Main fused persistent kernel: 256 threads, 8 warps, warp tile 64x64 (GEMM1)
// ============================================================================
__global__ void __launch_bounds__(256, 1)
edgeconv_main(const float* __restrict__ x,
              const void* __restrict__ ei,
              const float* __restrict__ ea,
              const float* __restrict__ b1,
              float* __restrict__ out) {
    extern __shared__ char smem[];
    const int tid  = threadIdx.x;
    const int wid  = tid >> 5;
    const int lane = tid & 31;
    const int wr   = wid >> 2;   // 0..1 : rows [64*wr, 64*wr+64)
    const int wc   = wid & 3;    // 0..3 : GEMM1 cols [64*wc,+64); GEMM2 [32*wc,+32)
    const int is64 = g_is64;

    int*   rows_s = (int*)(smem + SOFF_ROWS);
    int*   cols_s = (int*)(smem + SOFF_COLS);
    float* sB1    = (float*)(smem + SOFF_B1);
    float* Hbuf   = (float*)(smem + H_OFF);

    sB1[tid] = b1[tid];
    __syncthreads();

    // persistent b1 fragment registers (GEMM1 accumulator init)
    float2 b1v[8];
    #pragma unroll
    for (int nt = 0; nt < 8; nt++) {
        int cn = 64 * wc + 8 * nt + 2 * (lane & 3);
        b1v[nt] = *(const float2*)&sB1[cn];
    }

    const int rbase = 64 * wr + (lane >> 2);   // a-frag base row (low)

    for (int tile = blockIdx.x; tile < N_TILES; tile += GRID_MAIN) {
        const int ebase = tile * TILE_E;
        __syncthreads();   // prior tile's scatter reads of rows_s complete
        if (tid < 128) {
            if (is64) {
                rows_s[tid] = (int)((const long long*)ei)[ebase + tid];
                cols_s[tid] = (int)((const long long*)ei)[E_TOTAL + ebase + tid];
            } else {
                rows_s[tid] = ((const int*)ei)[ebase + tid];
                cols_s[tid] = ((const int*)ei)[E_TOTAL + ebase + tid];
            }
        }
        __syncthreads();

        // -------------------- GEMM1: acc[128,256] = msg @ W1 + b1 ----------
        float acc[4][8][4];
        #pragma unroll
        for (int mt = 0; mt < 4; mt++)
            #pragma unroll
            for (int nt = 0; nt < 8; nt++) {
                acc[mt][nt][0] = b1v[nt].x; acc[mt][nt][1] = b1v[nt].y;
                acc[mt][nt][2] = b1v[nt].x; acc[mt][nt][3] = b1v[nt].y;
            }

        #pragma unroll 1
        for (int c = 0; c < NCHUNK1; c++) {
            const int s = c & 1;
            {   // W1 chunk c -> wbuf[s] (flat 32KB copy, image pre-swizzled)
                const float4* src = (const float4*)(g_W1t + c * 8192);
                float4* dst = (float4*)(smem + WBUF_OFF + s * 32768);
                #pragma unroll
                for (int i = 0; i < 8; i++) dst[tid + i * 256] = src[tid + i * 256];
            }
            {   // gather msg chunk c: 128 edges x 32 cols, tf32, swizzled
                const int e = tid >> 1;
                const int half = tid & 1;
                const float* srcp;
                if (c < 4)      srcp = x  + (size_t)rows_s[e] * 128 + c * 32 + half * 16;
                else if (c < 8) srcp = x  + (size_t)cols_s[e] * 128 + (c - 4) * 32 + half * 16;
                else            srcp = ea + (size_t)(ebase + e) * 64 + (c - 8) * 32 + half * 16;
                float* abuf = (float*)(smem + ABUF_OFF + s * 16384);
                const int sw = (e & 7) << 2;
                #pragma unroll
                for (int j = 0; j < 4; j++) {
                    float4 v = *(const float4*)(srcp + j * 4);
                    uint4 t;
                    t.x = f2tf32(v.x); t.y = f2tf32(v.y);
                    t.z = f2tf32(v.z); t.w = f2tf32(v.w);
                    *(uint4*)&abuf[e * 32 + ((half * 16 + j * 4) ^ sw)] = t;
                }
            }
            __syncthreads();
            const float* A = (const float*)(smem + ABUF_OFF + s * 16384);
            const float* B = (const float*)(smem + WBUF_OFF + s * 32768);
            #pragma unroll
            for (int ks = 0; ks < 4; ks++) {
                uint32_t af[4][4];
                const int cc = ks * 8 + (lane & 3);
                #pragma unroll
                for (int mt = 0; mt < 4; mt++) {
                    const int r0 = rbase + 16 * mt;
                    const int sw = (r0 & 7) << 2;
                    af[mt][0] = __float_as_uint(A[r0 * 32 + (cc ^ sw)]);
                    af[mt][1] = __float_as_uint(A[(r0 + 8) * 32 + (cc ^ sw)]);
                    af[mt][2] = __float_as_uint(A[r0 * 32 + ((cc + 4) ^ sw)]);
                    af[mt][3] = __float_as_uint(A[(r0 + 8) * 32 + ((cc + 4) ^ sw)]);
                }
                const int pb = ks * 8 + 2 * (lane & 3);
                #pragma unroll
                for (int nt = 0; nt < 8; nt++) {
                    const int n = 64 * wc + 8 * nt + (lane >> 2);
                    float2 bv = *(const float2*)&B[n * 32 + (pb ^ ((n & 7) << 2))];
                    uint32_t bf[2] = { __float_as_uint(bv.x), __float_as_uint(bv.y) };
                    #pragma unroll
                    for (int mt = 0; mt < 4; mt++) mma8(acc[mt][nt], af[mt], bf);
                }
            }
        }

        // ------------- epilogue: h = tf32(relu(acc)) -> SMEM ---------------
        #pragma unroll
        for (int mt = 0; mt < 4; mt++) {
            const int r0 = rbase + 16 * mt;
            const int sw = (r0 & 7) << 2;
            #pragma unroll
            for (int nt = 0; nt < 8; nt++) {
                const int cn = 64 * wc + 8 * nt + 2 * (lane & 3);
                float2 lo, hi;
                lo.x = __uint_as_float(f2tf32(fmaxf(acc[mt][nt][0], 0.f)));
                lo.y = __uint_as_float(f2tf32(fmaxf(acc[mt][nt][1], 0.f)));
                hi.x = __uint_as_float(f2tf32(fmaxf(acc[mt][nt][2], 0.f)));
                hi.y = __uint_as_float(f2tf32(fmaxf(acc[mt][nt][3], 0.f)));
                *(float2*)&Hbuf[r0 * 256 + (cn ^ sw)] = lo;
                *(float2*)&Hbuf[(r0 + 8) * 256 + (cn ^ sw)] = hi;
            }
        }

        // -------------------- GEMM2: o[128,128] = h @ W2 -------------------
        float acc2[4][4][4];
        #pragma unroll
        for (int mt = 0; mt < 4; mt++)
            #pragma unroll
            for (int nt = 0; nt < 4; nt++)
                #pragma unroll
                for (int i = 0; i < 4; i++) acc2[mt][nt][i] = 0.f;

        #pragma unroll 1
        for (int j = 0; j < NCHUNK2; j++) {
            const int s = j & 1;
            {   // W2 chunk j -> 16KB slot inside WBUF region
                const float4* src = (const float4*)(g_W2t + j * 4096);
                float4* dst = (float4*)(smem + WBUF_OFF + s * 16384);
                #pragma unroll
                for (int i = 0; i < 4; i++) dst[tid + i * 256] = src[tid + i * 256];
            }
            __syncthreads();   // j==0 also publishes Hbuf
            const float* B2 = (const float*)(smem + WBUF_OFF + s * 16384);
            #pragma unroll
            for (int ks = 0; ks < 4; ks++) {
                uint32_t af[4][4];
                const int k = j * 32 + ks * 8 + (lane & 3);
                #pragma unroll
                for (int mt = 0; mt < 4; mt++) {
                    const int r0 = rbase + 16 * mt;
                    const int sw = (r0 & 7) << 2;
                    af[mt][0] = __float_as_uint(Hbuf[r0 * 256 + (k ^ sw)]);
                    af[mt][1] = __float_as_uint(Hbuf[(r0 + 8) * 256 + (k ^ sw)]);
                    af[mt][2] = __float_as_uint(Hbuf[r0 * 256 + ((k + 4) ^ sw)]);
                    af[mt][3] = __float_as_uint(Hbuf[(r0 + 8) * 256 + ((k + 4) ^ sw)]);
                }
                const int pb = ks * 8 + 2 * (lane & 3);
                #pragma unroll
                for (int nt = 0; nt < 4; nt++) {
                    const int n = 32 * wc + 8 * nt + (lane >> 2);
                    float2 bv = *(const float2*)&B2[n * 32 + (pb ^ ((n & 7) << 2))];
                    uint32_t bf[2] = { __float_as_uint(bv.x), __float_as_uint(bv.y) };
                    #pragma unroll
                    for (int mt = 0; mt < 4; mt++) mma8(acc2[mt][nt], af[mt], bf);
                }
            }
        }

        // -------------------- scatter: out[rows[m]] += o[m,:] --------------
        #pragma unroll
        for (int mt = 0; mt < 4; mt++) {
            const int r0 = rbase + 16 * mt;
            float* d0 = out + (size_t)rows_s[r0] * 128;
            float* d1 = out + (size_t)rows_s[r0 + 8] * 128;
            #pragma unroll
            for (int nt = 0; nt < 4; nt++) {
                const int cn = 32 * wc + 8 * nt + 2 * (lane & 3);
                red2(d0 + cn, acc2[mt][nt][0], acc2[mt][nt][1]);
                red2(d1 + cn, acc2[mt][nt][2], acc2[mt][nt][3]);
            }
        }
    }
}

// ============================================================================
// Launch
// ============================================================================
extern "C" void kernel_launch(void* const* d_in, const int* in_sizes, int n_in,
                              void* d_out, int out_size) {
    const float* x  = (const float*)d_in[0];
    const void*  ei = d_in[1];
    const float* ea = (const float*)d_in[2];
    const float* W1 = (const float*)d_in[3];
    const float* b1 = (const float*)d_in[4];
    const float* W2 = (const float*)d_in[5];
    const float* b2 = (const float*)d_in[6];
    float* out = (float*)d_out;

    cudaFuncSetAttribute(edgeconv_main,
                         cudaFuncAttributeMaxDynamicSharedMemorySize, SMEM_TOTAL);

    detect_kernel<<<1, 1>>>(ei);
    zero_kernel<<<(OUT_ELEMS + 255) / 256, 256>>>(out);
    prep_kernel<<<(320 * 256 + 256 * 128 + 255) / 256, 256>>>(W1, W2);
    deg_kernel<<<(E_TOTAL + 255) / 256, 256>>>(ei);
    edgeconv_main<<<GRID_MAIN, 256, SMEM_TOTAL>>>(x, ei, ea, b1, out);
    bias_kernel<<<(OUT_ELEMS + 255) / 256, 256>>>(out, b2);
}

// round 6
// speedup vs baseline: 1.3773x; 1.3773x over previous
#include <cuda_runtime.h>
#include <stdint.h>

// ============================================================================
//   msg[E,320] = [x[row] | x[col] | ea];  h = relu(msg@W1+b1)
//   hsum[n]    = sum_{e:row=n} h_e ;  degf[n] = deg(n)
//   out[n]     = hsum[n]@W2 + degf[n]*b2        (GEMM2 hoisted out of the edge
//                loop via linearity: sum o_e = (sum h_e)@W2)
// Legacy mma.sync.m16n8k8 tf32 (harness PTX target = compute_100; tcgen05 N/A).
// ============================================================================
#define E_TOTAL   640000
#define NN_NODES  100000
#define OUT_ELEMS (NN_NODES * 128)
#define TILE_E    128
#define N_TILES   (E_TOTAL / TILE_E)   // 5000
#define NCHUNK1   10                   // K1 = 320 = 10*32
#define GRID_MAIN 148
#define N_TILES2  782                  // ceil(100000/128)

// main kernel SMEM (bytes)
#define SOFF_ROWS 0        // 128 int
#define SOFF_COLS 512      // 128 int
#define SOFF_B1   1024     // 256 float
#define ABUF_OFF  3072     // 2 x 16384  (gathered msg chunk, tf32, swizzled)
#define WBUF_OFF  35840    // 2 x 32768  (W1 chunk double buffer, cp.async)
#define SMEM_MAIN 101376

// final kernel SMEM
#define F_B2_OFF   0       // 128 float
#define F_ABUF_OFF 1024    // 2 x 16384 (hsum chunk, tf32, swizzled)
#define F_W2_OFF   33792   // 131072 (all 8 W2 chunk images, resident)
#define SMEM_FIN   164864

// ============================================================================
// Device scratch (allocation-free)
// ============================================================================
__device__ __align__(16) float g_W1t[NCHUNK1 * 8192]; // pre-swizzled W1^T chunks
__device__ __align__(16) float g_W2t[8 * 4096];       // pre-swizzled W2^T chunks
__device__ __align__(16) float g_hsum[NN_NODES * 256];
__device__ float g_degf[NN_NODES];
__device__ int   g_is64;

// ============================================================================
// Helpers
// ============================================================================
__device__ __forceinline__ uint32_t smem_u32(const void* p) {
    uint32_t a;
    asm("{ .reg .u64 t; cvta.to.shared.u64 t, %1; cvt.u32.u64 %0, t; }"
        : "=r"(a) : "l"(p));
    return a;
}
__device__ __forceinline__ uint32_t f2tf32(float f) {
    uint32_t r;
    asm("cvt.rna.tf32.f32 %0, %1;" : "=r"(r) : "f"(f));
    return r;
}
__device__ __forceinline__ void mma8(float* d, const uint32_t* a, const uint32_t* b) {
    asm volatile(
        "mma.sync.aligned.m16n8k8.row.col.f32.tf32.tf32.f32 "
        "{%0,%1,%2,%3}, {%4,%5,%6,%7}, {%8,%9}, {%0,%1,%2,%3};"
        : "+f"(d[0]), "+f"(d[1]), "+f"(d[2]), "+f"(d[3])
        : "r"(a[0]), "r"(a[1]), "r"(a[2]), "r"(a[3]), "r"(b[0]), "r"(b[1]));
}
__device__ __forceinline__ void red2(float* p, float v0, float v1) {
    asm volatile("red.global.add.v2.f32 [%0], {%1, %2};"
                 :: "l"(p), "f"(v0), "f"(v1) : "memory");
}
__device__ __forceinline__ void red1(float* p, float v) {
    asm volatile("red.global.add.f32 [%0], %1;" :: "l"(p), "f"(v) : "memory");
}
#define CP_COMMIT()  asm volatile("cp.async.commit_group;" ::: "memory")
#define CP_WAIT(N)   asm volatile("cp.async.wait_group %0;" :: "n"(N) : "memory")
__device__ __forceinline__ void cp16(uint32_t dst, const void* src) {
    asm volatile("cp.async.cg.shared.global [%0], [%1], 16;"
                 :: "r"(dst), "l"(src) : "memory");
}
// W-chunk in-row position permutation: (k, k+4) adjacent -> one LDS.64 per B frag
__device__ __host__ __forceinline__ int wpos(int kk) {
    return ((kk >> 3) << 3) + ((kk & 3) << 1) + ((kk >> 2) & 1);
}

// ============================================================================
// Setup: zero hsum/degf, build weight images, probe edge_index dtype
// ============================================================================
__global__ void setup_kernel(const void* ei, const float* __restrict__ W1,
                             const float* __restrict__ W2) {
    int i = blockIdx.x * 256 + threadIdx.x;
    if (i == 0) {   // int64 values <2^31 => every odd 32-bit word is 0
        const unsigned* w = (const unsigned*)ei;
        int is64 = 1;
        for (int t = 0; t < 64; t++)
            if (w[2 * t + 1] != 0) { is64 = 0; break; }
        g_is64 = is64;
    }
    if (i < NN_NODES) g_degf[i] = 0.f;
    if (i < NN_NODES * 256) g_hsum[i] = 0.f;
    if (i < 320 * 256) {
        int k = i >> 8, n = i & 255;
        int idx = n * 32 + (wpos(k & 31) ^ ((n & 7) << 2));
        g_W1t[(k >> 5) * 8192 + idx] = __uint_as_float(f2tf32(W1[i]));
    } else if (i < 320 * 256 + 256 * 128) {
        int j = i - 320 * 256;
        int k = j >> 7, n = j & 127;
        int idx = n * 32 + (wpos(k & 31) ^ ((n & 7) << 2));
        g_W2t[(k >> 5) * 4096 + idx] = __uint_as_float(f2tf32(W2[j]));
    }
}

// ============================================================================
// Main: gather -> GEMM1(tf32, cp.async-pipelined) -> relu -> RED h to g_hsum
// ============================================================================
__global__ void __launch_bounds__(256, 1)
edgeconv_g1(const float* __restrict__ x,
            const void* __restrict__ ei,
            const float* __restrict__ ea,
            const float* __restrict__ b1) {
    extern __shared__ char smem[];
    const uint32_t sb = smem_u32(smem);
    const int tid  = threadIdx.x;
    const int wid  = tid >> 5;
    const int lane = tid & 31;
    const int wr   = wid >> 2;   // rows [64*wr, +64)
    const int wc   = wid & 3;    // cols [64*wc, +64)
    const int is64 = g_is64;

    int*   rows_s = (int*)(smem + SOFF_ROWS);
    int*   cols_s = (int*)(smem + SOFF_COLS);
    float* sB1    = (float*)(smem + SOFF_B1);

    sB1[tid] = b1[tid];
    __syncthreads();

    float2 b1v[8];
    #pragma unroll
    for (int nt = 0; nt < 8; nt++)
        b1v[nt] = *(const float2*)&sB1[64 * wc + 8 * nt + 2 * (lane & 3)];

    const int rbase = 64 * wr + (lane >> 2);
    const int e     = tid >> 1;
    const int half  = tid & 1;
    const int swA   = (e & 7) << 2;

    for (int tile = blockIdx.x; tile < N_TILES; tile += GRID_MAIN) {
        const int ebase = tile * TILE_E;
        __syncthreads();   // prior tile fully drained (rows_s, abuf, wbuf free)
        if (tid < 128) {
            if (is64) {
                rows_s[tid] = (int)((const long long*)ei)[ebase + tid];
                cols_s[tid] = (int)((const long long*)ei)[E_TOTAL + ebase + tid];
            } else {
                rows_s[tid] = ((const int*)ei)[ebase + tid];
                cols_s[tid] = ((const int*)ei)[E_TOTAL + ebase + tid];
            }
        }
        // stage W chunks 0,1 (no indices needed)
        {
            const char* s0 = (const char*)g_W1t;
            #pragma unroll
            for (int i = 0; i < 8; i++)
                cp16(sb + WBUF_OFF + tid * 16 + i * 4096, s0 + tid * 16 + i * 4096);
            CP_COMMIT();
            #pragma unroll
            for (int i = 0; i < 8; i++)
                cp16(sb + WBUF_OFF + 32768 + tid * 16 + i * 4096,
                     s0 + 32768 + tid * 16 + i * 4096);
            CP_COMMIT();
        }
        __syncthreads();   // indices visible

        float4 v[4];
        // gather chunk 0, store; gather chunk 1, hold in regs
        {
            const float* p = x + (size_t)rows_s[e] * 128 + half * 16;
            #pragma unroll
            for (int j = 0; j < 4; j++) v[j] = *(const float4*)(p + j * 4);
            float* ab = (float*)(smem + ABUF_OFF);
            #pragma unroll
            for (int j = 0; j < 4; j++) {
                uint4 t;
                t.x = f2tf32(v[j].x); t.y = f2tf32(v[j].y);
                t.z = f2tf32(v[j].z); t.w = f2tf32(v[j].w);
                *(uint4*)&ab[e * 32 + ((half * 16 + j * 4) ^ swA)] = t;
            }
            p = x + (size_t)rows_s[e] * 128 + 32 + half * 16;
            #pragma unroll
            for (int j = 0; j < 4; j++) v[j] = *(const float4*)(p + j * 4);
        }
        CP_WAIT(1);        // W0 arrived
        __syncthreads();   // A0 visible

        float acc[4][8][4];
        #pragma unroll
        for (int mt = 0; mt < 4; mt++)
            #pragma unroll
            for (int nt = 0; nt < 8; nt++) {
                acc[mt][nt][0] = b1v[nt].x; acc[mt][nt][1] = b1v[nt].y;
                acc[mt][nt][2] = b1v[nt].x; acc[mt][nt][3] = b1v[nt].y;
            }

        #pragma unroll 1
        for (int c = 0; c < NCHUNK1; c++) {
            const int s = c & 1;
            // ---- MMA on chunk c ----
            const float* A = (const float*)(smem + ABUF_OFF + s * 16384);
            const float* B = (const float*)(smem + WBUF_OFF + s * 32768);
            #pragma unroll
            for (int ks = 0; ks < 4; ks++) {
                uint32_t af[4][4];
                const int cc = ks * 8 + (lane & 3);
                #pragma unroll
                for (int mt = 0; mt < 4; mt++) {
                    const int r0 = rbase + 16 * mt;
                    const int sw = (r0 & 7) << 2;
                    af[mt][0] = __float_as_uint(A[r0 * 32 + (cc ^ sw)]);
                    af[mt][1] = __float_as_uint(A[(r0 + 8) * 32 + (cc ^ sw)]);
                    af[mt][2] = __float_as_uint(A[r0 * 32 + ((cc + 4) ^ sw)]);
                    af[mt][3] = __float_as_uint(A[(r0 + 8) * 32 + ((cc + 4) ^ sw)]);
                }
                const int pb = ks * 8 + 2 * (lane & 3);
                #pragma unroll
                for (int nt = 0; nt < 8; nt++) {
                    const int n = 64 * wc + 8 * nt + (lane >> 2);
                    float2 bv = *(const float2*)&B[n * 32 + (pb ^ ((n & 7) << 2))];
                    uint32_t bf[2] = { __float_as_uint(bv.x), __float_as_uint(bv.y) };
                    #pragma unroll
                    for (int mt = 0; mt < 4; mt++) mma8(acc[mt][nt], af[mt], bf);
                }
            }
            // ---- stage A[c+1] from regs, prefetch A[c+2] ----
            if (c < 9) {
                float* ab = (float*)(smem + ABUF_OFF + (s ^ 1) * 16384);
                #pragma unroll
                for (int j = 0; j < 4; j++) {
                    uint4 t;
                    t.x = f2tf32(v[j].x); t.y = f2tf32(v[j].y);
                    t.z = f2tf32(v[j].z); t.w = f2tf32(v[j].w);
                    *(uint4*)&ab[e * 32 + ((half * 16 + j * 4) ^ swA)] = t;
                }
                if (c < 8) {
                    const int c2 = c + 2;
                    const float* p;
                    if (c2 < 4)      p = x  + (size_t)rows_s[e] * 128 + c2 * 32 + half * 16;
                    else if (c2 < 8) p = x  + (size_t)cols_s[e] * 128 + (c2 - 4) * 32 + half * 16;
                    else             p = ea + (size_t)(ebase + e) * 64 + (c2 - 8) * 32 + half * 16;
                    #pragma unroll
                    for (int j = 0; j < 4; j++) v[j] = *(const float4*)(p + j * 4);
                }
            }
            CP_WAIT(0);        // W[c+1] delivered (this thread's slices)
            __syncthreads();   // everyone's A[c+1]/W[c+1] visible; wbuf[s] free
            if (c < 8) {       // stage W[c+2] into the buffer just freed
                const char* s0 = (const char*)g_W1t + (size_t)(c + 2) * 32768;
                #pragma unroll
                for (int i = 0; i < 8; i++)
                    cp16(sb + WBUF_OFF + s * 32768 + tid * 16 + i * 4096,
                         s0 + tid * 16 + i * 4096);
                CP_COMMIT();
            }
        }

        // ---- scatter: hsum[rows[m]] += relu(acc); degf[rows[m]] += 1 ----
        #pragma unroll
        for (int mt = 0; mt < 4; mt++) {
            const int r0 = rbase + 16 * mt;
            float* h0 = g_hsum + (size_t)rows_s[r0] * 256;
            float* h1 = g_hsum + (size_t)rows_s[r0 + 8] * 256;
            #pragma unroll
            for (int nt = 0; nt < 8; nt++) {
                const int cn = 64 * wc + 8 * nt + 2 * (lane & 3);
                red2(h0 + cn, fmaxf(acc[mt][nt][0], 0.f), fmaxf(acc[mt][nt][1], 0.f));
                red2(h1 + cn, fmaxf(acc[mt][nt][2], 0.f), fmaxf(acc[mt][nt][3], 0.f));
            }
            if (wc == 0 && (lane & 3) == 0) {
                red1(g_degf + rows_s[r0], 1.0f);
                red1(g_degf + rows_s[r0 + 8], 1.0f);
            }
        }
    }
}

// ============================================================================
// Final: out[n,:] = tf32(hsum[n]) @ W2 + degf[n]*b2   (dense [100k,256]x[256,128])
// ============================================================================
__global__ void __launch_bounds__(256, 1)
edgeconv_g2(const float* __restrict__ b2, float* __restrict__ out) {
    extern __shared__ char smem[];
    const int tid  = threadIdx.x;
    const int wid  = tid >> 5;
    const int lane = tid & 31;
    const int wr   = wid >> 1;   // rows [32*wr, +32)
    const int wc   = wid & 1;    // cols [64*wc, +64)

    float* sB2 = (float*)(smem + F_B2_OFF);
    if (tid < 128) sB2[tid] = b2[tid];
    {   // resident W2 images (all 8 chunks, 128KB)
        const float4* src = (const float4*)g_W2t;
        float4* dst = (float4*)(smem + F_W2_OFF);
        #pragma unroll
        for (int i = 0; i < 32; i++) dst[tid + i * 256] = src[tid + i * 256];
    }
    __syncthreads();

    float2 b2v[8];
    #pragma unroll
    for (int nt = 0; nt < 8; nt++)
        b2v[nt] = *(const float2*)&sB2[64 * wc + 8 * nt + 2 * (lane & 3)];

    const int rbase = 32 * wr + (lane >> 2);
    const int e     = tid >> 1;
    const int half  = tid & 1;
    const int swA   = (e & 7) << 2;

    for (int tile = blockIdx.x; tile < N_TILES2; tile += GRID_MAIN) {
        const int rg = tile * 128 + e;         // this thread's source row
        const bool ok = rg < NN_NODES;
        float4 v[4];

        // prologue: chunk 0 -> abuf0; chunk 1 -> regs
        {
            const float* p = g_hsum + (size_t)rg * 256 + half * 16;
            #pragma unroll
            for (int j = 0; j < 4; j++)
                v[j] = ok ? *(const float4*)(p + j * 4) : make_float4(0, 0, 0, 0);
            float* ab = (float*)(smem + F_ABUF_OFF);
            #pragma unroll
            for (int j = 0; j < 4; j++) {
                uint4 t;
                t.x = f2tf32(v[j].x); t.y = f2tf32(v[j].y);
                t.z = f2tf32(v[j].z); t.w = f2tf32(v[j].w);
                *(uint4*)&ab[e * 32 + ((half * 16 + j * 4) ^ swA)] = t;
            }
            p = g_hsum + (size_t)rg * 256 + 32 + half * 16;
            #pragma unroll
            for (int j = 0; j < 4; j++)
                v[j] = ok ? *(const float4*)(p + j * 4) : make_float4(0, 0, 0, 0);
        }
        __syncthreads();

        float acc[2][8][4];
        #pragma unroll
        for (int mt = 0; mt < 2; mt++)
            #pragma unroll
            for (int nt = 0; nt < 8; nt++)
                #pragma unroll
                for (int i = 0; i < 4; i++) acc[mt][nt][i] = 0.f;

        #pragma unroll 1
        for (int j = 0; j < 8; j++) {
            const int s = j & 1;
            const float* A = (const float*)(smem + F_ABUF_OFF + s * 16384);
            const float* B = (const float*)(smem + F_W2_OFF + j * 16384);
            #pragma unroll
            for (int ks = 0; ks < 4; ks++) {
                uint32_t af[2][4];
                const int cc = ks * 8 + (lane & 3);
                #pragma unroll
                for (int mt = 0; mt < 2; mt++) {
                    const int r0 = rbase + 16 * mt;
                    const int sw = (r0 & 7) << 2;
                    af[mt][0] = __float_as_uint(A[r0 * 32 + (cc ^ sw)]);
                    af[mt][1] = __float_as_uint(A[(r0 + 8) * 32 + (cc ^ sw)]);
                    af[mt][2] = __float_as_uint(A[r0 * 32 + ((cc + 4) ^ sw)]);
                    af[mt][3] = __float_as_uint(A[(r0 + 8) * 32 + ((cc + 4) ^ sw)]);
                }
                const int pb = ks * 8 + 2 * (lane & 3);
                #pragma unroll
                for (int nt = 0; nt < 8; nt++) {
                    const int n = 64 * wc + 8 * nt + (lane >> 2);
                    float2 bv = *(const float2*)&B[n * 32 + (pb ^ ((n & 7) << 2))];
                    uint32_t bf[2] = { __float_as_uint(bv.x), __float_as_uint(bv.y) };
                    #pragma unroll
                    for (int mt = 0; mt < 2; mt++) mma8(acc[mt][nt], af[mt], bf);
                }
            }
            if (j < 7) {
                float* ab = (float*)(smem + F_ABUF_OFF + (s ^ 1) * 16384);
                #pragma unroll
                for (int jj = 0; jj < 4; jj++) {
                    uint4 t;
                    t.x = f2tf32(v[jj].x); t.y = f2tf32(v[jj].y);
                    t.z = f2tf32(v[jj].z); t.w = f2tf32(v[jj].w);
                    *(uint4*)&ab[e * 32 + ((half * 16 + jj * 4) ^ swA)] = t;
                }
                if (j < 6) {
                    const float* p = g_hsum + (size_t)rg * 256 + (j + 2) * 32 + half * 16;
                    #pragma unroll
                    for (int jj = 0; jj < 4; jj++)
                        v[jj] = ok ? *(const float4*)(p + jj * 4) : make_float4(0, 0, 0, 0);
                }
            }
            __syncthreads();
        }

        // store out
        #pragma unroll
        for (int mt = 0; mt < 2; mt++) {
            const int r0 = tile * 128 + rbase + 16 * mt;
            const bool ok0 = r0 < NN_NODES;
            const bool ok1 = (r0 + 8) < NN_NODES;
            const float dg0 = ok0 ? g_degf[r0] : 0.f;
            const float dg1 = ok1 ? g_degf[r0 + 8] : 0.f;
            #pragma unroll
            for (int nt = 0; nt < 8; nt++) {
                const int cn = 64 * wc + 8 * nt + 2 * (lane & 3);
                if (ok0) {
                    float2 o = make_float2(acc[mt][nt][0] + dg0 * b2v[nt].x,
                                           acc[mt][nt][1] + dg0 * b2v[nt].y);
                    *(float2*)(out + (size_t)r0 * 128 + cn) = o;
                }
                if (ok1) {
                    float2 o = make_float2(acc[mt][nt][2] + dg1 * b2v[nt].x,
                                           acc[mt][nt][3] + dg1 * b2v[nt].y);
                    *(float2*)(out + (size_t)(r0 + 8) * 128 + cn) = o;
                }
            }
        }
    }
}

// ============================================================================
// Launch
// ============================================================================
extern "C" void kernel_launch(void* const* d_in, const int* in_sizes, int n_in,
                              void* d_out, int out_size) {
    const float* x  = (const float*)d_in[0];
    const void*  ei = d_in[1];
    const float* ea = (const float*)d_in[2];
    const float* W1 = (const float*)d_in[3];
    const float* b1 = (const float*)d_in[4];
    const float* W2 = (const float*)d_in[5];
    const float* b2 = (const float*)d_in[6];
    float* out = (float*)d_out;

    cudaFuncSetAttribute(edgeconv_g1,
                         cudaFuncAttributeMaxDynamicSharedMemorySize, SMEM_MAIN);
    cudaFuncSetAttribute(edgeconv_g2,
                         cudaFuncAttributeMaxDynamicSharedMemorySize, SMEM_FIN);

    setup_kernel<<<(NN_NODES * 256) / 256, 256>>>(ei, W1, W2);
    edgeconv_g1<<<GRID_MAIN, 256, SMEM_MAIN>>>(x, ei, ea, b1);
    edgeconv_g2<<<GRID_MAIN, 256, SMEM_FIN>>>(b2, out);
}

// round 9
// speedup vs baseline: 1.8916x; 1.3734x over previous
#include <cuda_runtime.h>
#include <cuda_fp16.h>
#include <stdint.h>

// ============================================================================
//   msg[E,320] = [x[row] | x[col] | ea];  h = relu(msg@W1+b1)
//   hsum[n]    = sum_{e:row=n} h_e ;  degf[n] = deg(n)
//   out[n]     = hsum[n]@W2 + degf[n]*b2   (GEMM2 hoisted via linearity)
// fp16 mma.sync.m16n8k16, f32 accumulate. Operand SMEM layout [ks][row][8w]
// with z = (row&4)^(ks<<1) pair-swizzle: all LDS/STS phases conflict-free.
// ============================================================================
#define E_TOTAL   640000
#define NN_NODES  100000
#define OUT_ELEMS (NN_NODES * 128)
#define TILE_E    128
#define N_TILES   (E_TOTAL / TILE_E)   // 5000
#define NCHUNK1   10                   // K1 = 320 = 10*32
#define GRID_MAIN 148
#define N_TILES2  782                  // ceil(100000/128)

// g1 SMEM (bytes)
#define SOFF_ROWS 0        // 128 int
#define SOFF_COLS 512      // 128 int
#define SOFF_B1   1024     // 256 float
#define ABUF_OFF  2048     // 2 x 8192  (msg chunk, fp16: [2][128][8] words)
#define WBUF_OFF  18432    // 2 x 16384 (W1 chunk, fp16: [2][256][8] words)
#define SMEM_MAIN 51200

// g2 SMEM
#define F_B2_OFF   0       // 128 float
#define F_ABUF_OFF 1024    // 2 x 8192 (hsum chunk: [2][128][8] words)
#define F_W2_OFF   17408   // 65536 (8 chunks x [2][128][8] words)
#define SMEM_FIN   82944

// ============================================================================
// Device scratch (allocation-free)
// ============================================================================
__device__ __align__(16) __half g_W1h[NCHUNK1 * 8192]; // 10 chunks x 4096 words
__device__ __align__(16) __half g_W2h[8 * 4096];       // 8 chunks x 2048 words
__device__ __align__(16) float  g_hsum[NN_NODES * 256];
__device__ float g_degf[NN_NODES];
__device__ int   g_is64;

// ============================================================================
// Helpers
// ============================================================================
__device__ __forceinline__ uint32_t smem_u32(const void* p) {
    uint32_t a;
    asm("{ .reg .u64 t; cvta.to.shared.u64 t, %1; cvt.u32.u64 %0, t; }"
        : "=r"(a) : "l"(p));
    return a;
}
// pack (lo, hi) -> f16x2 word (lo in low 16 bits)
__device__ __forceinline__ uint32_t f2h2(float lo, float hi) {
    uint32_t r;
    asm("cvt.rn.f16x2.f32 %0, %1, %2;" : "=r"(r) : "f"(hi), "f"(lo));
    return r;
}
__device__ __forceinline__ void mma16(float* d, const uint32_t* a,
                                      uint32_t b0, uint32_t b1) {
    asm volatile(
        "mma.sync.aligned.m16n8k16.row.col.f32.f16.f16.f32 "
        "{%0,%1,%2,%3}, {%4,%5,%6,%7}, {%8,%9}, {%0,%1,%2,%3};"
        : "+f"(d[0]), "+f"(d[1]), "+f"(d[2]), "+f"(d[3])
        : "r"(a[0]), "r"(a[1]), "r"(a[2]), "r"(a[3]), "r"(b0), "r"(b1));
}
__device__ __forceinline__ void red2(float* p, float v0, float v1) {
    asm volatile("red.global.add.v2.f32 [%0], {%1, %2};"
                 :: "l"(p), "f"(v0), "f"(v1) : "memory");
}
__device__ __forceinline__ void red1(float* p, float v) {
    asm volatile("red.global.add.f32 [%0], %1;" :: "l"(p), "f"(v) : "memory");
}
#define CP_COMMIT()  asm volatile("cp.async.commit_group;" ::: "memory")
#define CP_WAIT(N)   asm volatile("cp.async.wait_group %0;" :: "n"(N) : "memory")
__device__ __forceinline__ void cp16(uint32_t dst, const void* src) {
    asm volatile("cp.async.cg.shared.global [%0], [%1], 16;"
                 :: "r"(dst), "l"(src) : "memory");
}

// Stage one k32 chunk row-half (16 f32, k = 16*ks + 0..15) into the fp16 image.
// A layout: word = ks*1024 + row*8 + ((2s)^z) + hi  holds k-pair w = s + 4*hi,
// z = (row&4) ^ (ks<<1). Per half-warp STS.64 phase, each bank-octet's 4
// writers {row, row+4} x {ks0, ks1} get the 4 distinct slots -> conflict-free.
__device__ __forceinline__ void stage_row(uint32_t* ab, int e, int ks,
                                          const float4* v) {
    uint32_t* row = ab + ks * 1024 + e * 8;
    const int z = (e & 4) ^ (ks << 1);
    *(uint2*)&row[0 ^ z] = make_uint2(f2h2(v[0].x, v[0].y), f2h2(v[2].x, v[2].y));
    *(uint2*)&row[2 ^ z] = make_uint2(f2h2(v[0].z, v[0].w), f2h2(v[2].z, v[2].w));
    *(uint2*)&row[4 ^ z] = make_uint2(f2h2(v[1].x, v[1].y), f2h2(v[3].x, v[3].y));
    *(uint2*)&row[6 ^ z] = make_uint2(f2h2(v[1].z, v[1].w), f2h2(v[3].z, v[3].w));
}

// ============================================================================
// Setup: zero hsum/degf, build fp16 weight images, probe edge_index dtype
// ============================================================================
__global__ void setup_kernel(const void* ei, const float* __restrict__ W1,
                             const float* __restrict__ W2) {
    int i = blockIdx.x * 256 + threadIdx.x;
    if (i == 0) {   // int64 values <2^31 => every odd 32-bit word is 0
        const unsigned* w = (const unsigned*)ei;
        int is64 = 1;
        for (int t = 0; t < 64; t++)
            if (w[2 * t + 1] != 0) { is64 = 0; break; }
        g_is64 = is64;
    }
    if (i < NN_NODES) g_degf[i] = 0.f;
    if (i < NN_NODES * 256) g_hsum[i] = 0.f;
    if (i < 320 * 256) {
        int k = i >> 8, n = i & 255;
        int kc = k & 31, ks = kc >> 4, w = (kc & 15) >> 1;
        int z = (n & 4) ^ (ks << 1);
        int word = ks * 2048 + n * 8 + ((2 * (w & 3)) ^ z) + (w >> 2);
        g_W1h[(k >> 5) * 8192 + word * 2 + (kc & 1)] = __float2half_rn(W1[i]);
    } else if (i < 320 * 256 + 256 * 128) {
        int j = i - 320 * 256;
        int k = j >> 7, n = j & 127;
        int kc = k & 31, ks = kc >> 4, w = (kc & 15) >> 1;
        int z = (n & 4) ^ (ks << 1);
        int word = ks * 1024 + n * 8 + ((2 * (w & 3)) ^ z) + (w >> 2);
        g_W2h[(k >> 5) * 4096 + word * 2 + (kc & 1)] = __float2half_rn(W2[j]);
    }
}

// ============================================================================
// Main: gather -> GEMM1(fp16, cp.async-pipelined) -> relu -> RED h to g_hsum
// ============================================================================
__global__ void __launch_bounds__(256, 1)
edgeconv_g1(const float* __restrict__ x,
            const void* __restrict__ ei,
            const float* __restrict__ ea,
            const float* __restrict__ b1) {
    extern __shared__ char smem[];
    const uint32_t sb = smem_u32(smem);
    const int tid  = threadIdx.x;
    const int wid  = tid >> 5;
    const int lane = tid & 31;
    const int wr   = wid >> 2;   // rows [64*wr, +64)
    const int wc   = wid & 3;    // cols [64*wc, +64)
    const int is64 = g_is64;
    const int gq   = lane >> 2;              // quad id 0..7
    const int q2   = 2 * (lane & 3);
    const int zn   = gq & 4;                 // = r0&4 = n&4 for all mt/nt

    int*   rows_s = (int*)(smem + SOFF_ROWS);
    int*   cols_s = (int*)(smem + SOFF_COLS);
    float* sB1    = (float*)(smem + SOFF_B1);

    sB1[tid] = b1[tid];
    __syncthreads();

    float2 b1v[8];
    #pragma unroll
    for (int nt = 0; nt < 8; nt++)
        b1v[nt] = *(const float2*)&sB1[64 * wc + 8 * nt + 2 * (lane & 3)];

    const int rbase = 64 * wr + gq;
    const int e     = tid >> 1;
    const int half  = tid & 1;

    for (int tile = blockIdx.x; tile < N_TILES; tile += GRID_MAIN) {
        const int ebase = tile * TILE_E;
        __syncthreads();   // prior tile fully drained
        if (tid < 128) {
            if (is64) {
                rows_s[tid] = (int)((const long long*)ei)[ebase + tid];
                cols_s[tid] = (int)((const long long*)ei)[E_TOTAL + ebase + tid];
            } else {
                rows_s[tid] = ((const int*)ei)[ebase + tid];
                cols_s[tid] = ((const int*)ei)[E_TOTAL + ebase + tid];
            }
        }
        // stage W chunks 0,1 (16KB each)
        {
            const char* s0 = (const char*)g_W1h;
            #pragma unroll
            for (int i = 0; i < 4; i++)
                cp16(sb + WBUF_OFF + tid * 16 + i * 4096, s0 + tid * 16 + i * 4096);
            CP_COMMIT();
            #pragma unroll
            for (int i = 0; i < 4; i++)
                cp16(sb + WBUF_OFF + 16384 + tid * 16 + i * 4096,
                     s0 + 16384 + tid * 16 + i * 4096);
            CP_COMMIT();
        }
        __syncthreads();   // indices visible

        float4 v[4];
        {   // gather chunk 0 -> smem; chunk 1 -> regs
            const float* p = x + (size_t)rows_s[e] * 128 + half * 16;
            #pragma unroll
            for (int j = 0; j < 4; j++) v[j] = *(const float4*)(p + j * 4);
            stage_row((uint32_t*)(smem + ABUF_OFF), e, half, v);
            p = x + (size_t)rows_s[e] * 128 + 32 + half * 16;
            #pragma unroll
            for (int j = 0; j < 4; j++) v[j] = *(const float4*)(p + j * 4);
        }
        CP_WAIT(1);        // W0 arrived
        __syncthreads();   // A0 visible

        float acc[4][8][4];
        #pragma unroll
        for (int mt = 0; mt < 4; mt++)
            #pragma unroll
            for (int nt = 0; nt < 8; nt++) {
                acc[mt][nt][0] = b1v[nt].x; acc[mt][nt][1] = b1v[nt].y;
                acc[mt][nt][2] = b1v[nt].x; acc[mt][nt][3] = b1v[nt].y;
            }

        #pragma unroll 1
        for (int c = 0; c < NCHUNK1; c++) {
            const int s = c & 1;
            const uint32_t* A16 = (const uint32_t*)(smem + ABUF_OFF + s * 8192);
            const uint32_t* B16 = (const uint32_t*)(smem + WBUF_OFF + s * 16384);
            #pragma unroll
            for (int ks = 0; ks < 2; ks++) {
                const uint32_t* Aks = A16 + ks * 1024;
                const uint32_t* Bks = B16 + ks * 2048;
                const int qz = q2 ^ zn ^ (ks << 1);
                uint32_t af[4][4];
                #pragma unroll
                for (int mt = 0; mt < 4; mt++) {
                    const int r0 = rbase + 16 * mt;
                    uint2 lo = *(const uint2*)&Aks[r0 * 8 + qz];
                    uint2 hi = *(const uint2*)&Aks[(r0 + 8) * 8 + qz];
                    af[mt][0] = lo.x; af[mt][1] = hi.x;
                    af[mt][2] = lo.y; af[mt][3] = hi.y;
                }
                #pragma unroll
                for (int nt = 0; nt < 8; nt++) {
                    const int n = 64 * wc + 8 * nt + gq;
                    uint2 bv = *(const uint2*)&Bks[n * 8 + qz];
                    #pragma unroll
                    for (int mt = 0; mt < 4; mt++) mma16(acc[mt][nt], af[mt], bv.x, bv.y);
                }
            }
            // stage A[c+1] from regs, prefetch A[c+2]
            if (c < 9) {
                stage_row((uint32_t*)(smem + ABUF_OFF + (s ^ 1) * 8192), e, half, v);
                if (c < 8) {
                    const int c2 = c + 2;
                    const float* p;
                    if (c2 < 4)      p = x  + (size_t)rows_s[e] * 128 + c2 * 32 + half * 16;
                    else if (c2 < 8) p = x  + (size_t)cols_s[e] * 128 + (c2 - 4) * 32 + half * 16;
                    else             p = ea + (size_t)(ebase + e) * 64 + (c2 - 8) * 32 + half * 16;
                    #pragma unroll
                    for (int j = 0; j < 4; j++) v[j] = *(const float4*)(p + j * 4);
                }
            }
            CP_WAIT(0);        // W[c+1] delivered
            __syncthreads();   // A[c+1]/W[c+1] visible; wbuf[s] free
            if (c < 8) {       // stage W[c+2] into freed buffer
                const char* s0 = (const char*)g_W1h + (size_t)(c + 2) * 16384;
                #pragma unroll
                for (int i = 0; i < 4; i++)
                    cp16(sb + WBUF_OFF + s * 16384 + tid * 16 + i * 4096,
                         s0 + tid * 16 + i * 4096);
                CP_COMMIT();
            }
        }

        // scatter: hsum[rows[m]] += relu(acc); degf[rows[m]] += 1
        #pragma unroll
        for (int mt = 0; mt < 4; mt++) {
            const int r0 = rbase + 16 * mt;
            float* h0 = g_hsum + (size_t)rows_s[r0] * 256;
            float* h1 = g_hsum + (size_t)rows_s[r0 + 8] * 256;
            #pragma unroll
            for (int nt = 0; nt < 8; nt++) {
                const int cn = 64 * wc + 8 * nt + 2 * (lane & 3);
                red2(h0 + cn, fmaxf(acc[mt][nt][0], 0.f), fmaxf(acc[mt][nt][1], 0.f));
                red2(h1 + cn, fmaxf(acc[mt][nt][2], 0.f), fmaxf(acc[mt][nt][3], 0.f));
            }
            if (wc == 0 && (lane & 3) == 0) {
                red1(g_degf + rows_s[r0], 1.0f);
                red1(g_degf + rows_s[r0 + 8], 1.0f);
            }
        }
    }
}

// ============================================================================
// Final: out[n,:] = fp16(hsum[n]) @ W2 + degf[n]*b2  (dense 100k x 256 x 128)
// ============================================================================
__global__ void __launch_bounds__(256, 1)
edgeconv_g2(const float* __restrict__ b2, float* __restrict__ out) {
    extern __shared__ char smem[];
    const int tid  = threadIdx.x;
    const int wid  = tid >> 5;
    const int lane = tid & 31;
    const int wr   = wid >> 1;   // rows [32*wr, +32)
    const int wc   = wid & 1;    // cols [64*wc, +64)
    const int gq   = lane >> 2;
    const int q2   = 2 * (lane & 3);
    const int zn   = gq & 4;

    float* sB2 = (float*)(smem + F_B2_OFF);
    if (tid < 128) sB2[tid] = b2[tid];
    {   // resident W2 images (64KB)
        const float4* src = (const float4*)g_W2h;
        float4* dst = (float4*)(smem + F_W2_OFF);
        #pragma unroll
        for (int i = 0; i < 16; i++) dst[tid + i * 256] = src[tid + i * 256];
    }
    __syncthreads();

    float2 b2v[8];
    #pragma unroll
    for (int nt = 0; nt < 8; nt++)
        b2v[nt] = *(const float2*)&sB2[64 * wc + 8 * nt + 2 * (lane & 3)];

    const int rbase = 32 * wr + gq;
    const int e     = tid >> 1;
    const int half  = tid & 1;

    for (int tile = blockIdx.x; tile < N_TILES2; tile += GRID_MAIN) {
        const int rg = tile * 128 + e;
        const bool ok = rg < NN_NODES;
        float4 v[4];

        {   // chunk 0 -> smem; chunk 1 -> regs
            const float* p = g_hsum + (size_t)rg * 256 + half * 16;
            #pragma unroll
            for (int j = 0; j < 4; j++)
                v[j] = ok ? *(const float4*)(p + j * 4) : make_float4(0, 0, 0, 0);
            stage_row((uint32_t*)(smem + F_ABUF_OFF), e, half, v);
            p = g_hsum + (size_t)rg * 256 + 32 + half * 16;
            #pragma unroll
            for (int j = 0; j < 4; j++)
                v[j] = ok ? *(const float4*)(p + j * 4) : make_float4(0, 0, 0, 0);
        }
        __syncthreads();

        float acc[2][8][4];
        #pragma unroll
        for (int mt = 0; mt < 2; mt++)
            #pragma unroll
            for (int nt = 0; nt < 8; nt++)
                #pragma unroll
                for (int i = 0; i < 4; i++) acc[mt][nt][i] = 0.f;

        #pragma unroll 1
        for (int j = 0; j < 8; j++) {
            const int s = j & 1;
            const uint32_t* A16 = (const uint32_t*)(smem + F_ABUF_OFF + s * 8192);
            const uint32_t* B16 = (const uint32_t*)(smem + F_W2_OFF + j * 8192);
            #pragma unroll
            for (int ks = 0; ks < 2; ks++) {
                const uint32_t* Aks = A16 + ks * 1024;
                const uint32_t* Bks = B16 + ks * 1024;
                const int qz = q2 ^ zn ^ (ks << 1);
                uint32_t af[2][4];
                #pragma unroll
                for (int mt = 0; mt < 2; mt++) {
                    const int r0 = rbase + 16 * mt;
                    uint2 lo = *(const uint2*)&Aks[r0 * 8 + qz];
                    uint2 hi = *(const uint2*)&Aks[(r0 + 8) * 8 + qz];
                    af[mt][0] = lo.x; af[mt][1] = hi.x;
                    af[mt][2] = lo.y; af[mt][3] = hi.y;
                }
                #pragma unroll
                for (int nt = 0; nt < 8; nt++) {
                    const int n = 64 * wc + 8 * nt + gq;
                    uint2 bv = *(const uint2*)&Bks[n * 8 + qz];
                    #pragma unroll
                    for (int mt = 0; mt < 2; mt++) mma16(acc[mt][nt], af[mt], bv.x, bv.y);
                }
            }
            if (j < 7) {
                stage_row((uint32_t*)(smem + F_ABUF_OFF + (s ^ 1) * 8192), e, half, v);
                if (j < 6) {
                    const float* p = g_hsum + (size_t)rg * 256 + (j + 2) * 32 + half * 16;
                    #pragma unroll
                    for (int jj = 0; jj < 4; jj++)
                        v[jj] = ok ? *(const float4*)(p + jj * 4) : make_float4(0, 0, 0, 0);
                }
            }
            __syncthreads();
        }

        #pragma unroll
        for (int mt = 0; mt < 2; mt++) {
            const int r0 = tile * 128 + rbase + 16 * mt;
            const bool ok0 = r0 < NN_NODES;
            const bool ok1 = (r0 + 8) < NN_NODES;
            const float dg0 = ok0 ? g_degf[r0] : 0.f;
            const float dg1 = ok1 ? g_degf[r0 + 8] : 0.f;
            #pragma unroll
            for (int nt = 0; nt < 8; nt++) {
                const int cn = 64 * wc + 8 * nt + 2 * (lane & 3);
                if (ok0) {
                    float2 o = make_float2(acc[mt][nt][0] + dg0 * b2v[nt].x,
                                           acc[mt][nt][1] + dg0 * b2v[nt].y);
                    *(float2*)(out + (size_t)r0 * 128 + cn) = o;
                }
                if (ok1) {
                    float2 o = make_float2(acc[mt][nt][2] + dg1 * b2v[nt].x,
                                           acc[mt][nt][3] + dg1 * b2v[nt].y);
                    *(float2*)(out + (size_t)(r0 + 8) * 128 + cn) = o;
                }
            }
        }
    }
}

// ============================================================================
// Launch
// ============================================================================
extern "C" void kernel_launch(void* const* d_in, const int* in_sizes, int n_in,
                              void* d_out, int out_size) {
    const float* x  = (const float*)d_in[0];
    const void*  ei = d_in[1];
    const float* ea = (const float*)d_in[2];
    const float* W1 = (const float*)d_in[3];
    const float* b1 = (const float*)d_in[4];
    const float* W2 = (const float*)d_in[5];
    const float* b2 = (const float*)d_in[6];
    float* out = (float*)d_out;

    cudaFuncSetAttribute(edgeconv_g1,
                         cudaFuncAttributeMaxDynamicSharedMemorySize, SMEM_MAIN);
    cudaFuncSetAttribute(edgeconv_g2,
                         cudaFuncAttributeMaxDynamicSharedMemorySize, SMEM_FIN);

    setup_kernel<<<(NN_NODES * 256) / 256, 256>>>(ei, W1, W2);
    edgeconv_g1<<<GRID_MAIN, 256, SMEM_MAIN>>>(x, ei, ea, b1);
    edgeconv_g2<<<GRID_MAIN, 256, SMEM_FIN>>>(b2, out);
}

// round 10
// speedup vs baseline: 2.0446x; 1.0809x over previous
#include <cuda_runtime.h>
#include <cuda_fp16.h>
#include <stdint.h>

// ============================================================================
//   h_e = relu(x[row]@W1a + x[col]@W1b + ea@W1c + b1)
//   Precompute u = x@W1a + b1, v = x@W1b  (per NODE, dense)        [g0]
//   Per edge: h = relu(u[row] + v[col] + ea@W1c); hsum[n] += h     [g1]
//   out[n] = hsum[n]@W2 + degf[n]*b2                               [g2]
// fp16 mma.sync.m16n8k16, f32 accumulate.
// ============================================================================
#define E_TOTAL   640000
#define NN_NODES  100000
#define OUT_ELEMS (NN_NODES * 128)
#define TILE_E    128
#define N_TILES   (E_TOTAL / TILE_E)   // 5000
#define GRID_MAIN 148
#define N_TILES0  1563                 // ceil(100000/64)
#define N_TILES2  782                  // ceil(100000/128)

// g0 SMEM
#define G0_A    0        // [8 planes][64 rows][8 words] = 16384 B
#define G0_WA   16384    // [8][256][8] words = 65536 B
#define G0_WB   81920    // 65536 B
#define G0_B1   147456   // 256 floats
#define SMEM_G0 148480

// g1 SMEM
#define G1_ROWS 0        // 128 int
#define G1_COLS 512      // 128 int
#define G1_WC   1024     // [4][256][8] words = 32768 B
#define G1_AEA  33792    // [4][128][8] words = 16384 B
#define G1_UV   50176    // 128 rows x 136 words x 4 B = 69632 B
#define SMEM_G1 119808

// g2 SMEM
#define F_B2_OFF   0
#define F_ABUF_OFF 1024  // 2 x 8192
#define F_W2_OFF   17408 // 65536
#define SMEM_FIN   82944

// ============================================================================
// Device scratch (allocation-free)
// ============================================================================
__device__ __align__(16) __half g_Wa[8 * 2048 * 2];   // W1a image [8ks][256][8w]
__device__ __align__(16) __half g_Wb[8 * 2048 * 2];   // W1b image
__device__ __align__(16) __half g_Wc[4 * 2048 * 2];   // W1c image [4ks][256][8w]
__device__ __align__(16) __half g_W2h[8 * 4096];      // W2 chunk images
__device__ __align__(16) __half g_u[NN_NODES * 256];  // u = x@W1a + b1 (fp16)
__device__ __align__(16) __half g_v[NN_NODES * 256];  // v = x@W1b
__device__ __align__(16) float  g_hsum[NN_NODES * 256];
__device__ float g_degf[NN_NODES];
__device__ int   g_is64;

// ============================================================================
// Helpers
// ============================================================================
__device__ __forceinline__ uint32_t f2h2(float lo, float hi) {
    uint32_t r;
    asm("cvt.rn.f16x2.f32 %0, %1, %2;" : "=r"(r) : "f"(hi), "f"(lo));
    return r;
}
__device__ __forceinline__ uint32_t hadd2u(uint32_t a, uint32_t b) {
    uint32_t r;
    asm("add.rn.f16x2 %0, %1, %2;" : "=r"(r) : "r"(a), "r"(b));
    return r;
}
__device__ __forceinline__ void mma16(float* d, const uint32_t* a,
                                      uint32_t b0, uint32_t b1) {
    asm volatile(
        "mma.sync.aligned.m16n8k16.row.col.f32.f16.f16.f32 "
        "{%0,%1,%2,%3}, {%4,%5,%6,%7}, {%8,%9}, {%0,%1,%2,%3};"
        : "+f"(d[0]), "+f"(d[1]), "+f"(d[2]), "+f"(d[3])
        : "r"(a[0]), "r"(a[1]), "r"(a[2]), "r"(a[3]), "r"(b0), "r"(b1));
}
__device__ __forceinline__ void red2(float* p, float v0, float v1) {
    asm volatile("red.global.add.v2.f32 [%0], {%1, %2};"
                 :: "l"(p), "f"(v0), "f"(v1) : "memory");
}
__device__ __forceinline__ void red1(float* p, float v) {
    asm volatile("red.global.add.f32 [%0], %1;" :: "l"(p), "f"(v) : "memory");
}

// Stage 16 consecutive k-values (one k16 plane) of one row into an operand
// image. word = ks*stride + row*8 + ((2s)^z) + hi, z = (row&4) ^ ((ks&1)<<1).
__device__ __forceinline__ void stage_row(uint32_t* ab, int row, int ks,
                                          int stride, const float4* v) {
    uint32_t* rp = ab + ks * stride + row * 8;
    const int z = (row & 4) ^ ((ks & 1) << 1);
    *(uint2*)&rp[0 ^ z] = make_uint2(f2h2(v[0].x, v[0].y), f2h2(v[2].x, v[2].y));
    *(uint2*)&rp[2 ^ z] = make_uint2(f2h2(v[0].z, v[0].w), f2h2(v[2].z, v[2].w));
    *(uint2*)&rp[4 ^ z] = make_uint2(f2h2(v[1].x, v[1].y), f2h2(v[3].x, v[3].y));
    *(uint2*)&rp[6 ^ z] = make_uint2(f2h2(v[1].z, v[1].w), f2h2(v[3].z, v[3].w));
}

// Matching weight-image element store (setup side).
__device__ __forceinline__ void img_store(__half* img, int kk, int n,
                                          int plane_words, float val) {
    const int ks = kk >> 4, w = (kk & 15) >> 1;
    const int z = (n & 4) ^ ((ks & 1) << 1);
    const int word = ks * plane_words + n * 8 + ((2 * (w & 3)) ^ z) + (w >> 2);
    img[word * 2 + (kk & 1)] = __float2half_rn(val);
}

// ============================================================================
// Setup: zero hsum/degf (vectorized), build weight images, probe idx dtype
// ============================================================================
#define SETUP_BLOCKS 25840
__global__ void setup_kernel(const void* ei, const float* __restrict__ W1,
                             const float* __restrict__ W2) {
    int i = blockIdx.x * 256 + threadIdx.x;
    if (i < 6400000) {
        ((float4*)g_hsum)[i] = make_float4(0.f, 0.f, 0.f, 0.f);
        return;
    }
    i -= 6400000;
    if (i < NN_NODES) { g_degf[i] = 0.f; return; }
    i -= NN_NODES;
    if (i < 32768) {                       // W1a: k = 0..127
        int kk = i >> 8, n = i & 255;
        img_store(g_Wa, kk, n, 2048, W1[kk * 256 + n]);
    } else if (i < 65536) {                // W1b: k = 128..255
        int j = i - 32768;
        int kk = j >> 8, n = j & 255;
        img_store(g_Wb, kk, n, 2048, W1[(kk + 128) * 256 + n]);
    } else if (i < 81920) {                // W1c: k = 256..319
        int j = i - 65536;
        int kk = j >> 8, n = j & 255;
        img_store(g_Wc, kk, n, 2048, W1[(kk + 256) * 256 + n]);
    } else if (i < 114688) {               // W2: chunk images
        int j = i - 81920;
        int k = j >> 7, n = j & 127;
        img_store(g_W2h + (k >> 5) * 4096, k & 31, n, 1024, W2[k * 128 + n]);
    } else if (i == 114688) {              // int64 probe
        const unsigned* w = (const unsigned*)ei;
        int is64 = 1;
        for (int t = 0; t < 64; t++)
            if (w[2 * t + 1] != 0) { is64 = 0; break; }
        g_is64 = is64;
    }
}

// ============================================================================
// g0: u[n] = fp16(x[n]@W1a + b1), v[n] = fp16(x[n]@W1b). Tile = 64 rows.
// Warps: rowg = wid&1 (32 rows), colh = (wid>>1)&1 (128 cols), outs = wid>>2.
// ============================================================================
__global__ void __launch_bounds__(256, 1)
edgeconv_g0(const float* __restrict__ x, const float* __restrict__ b1) {
    extern __shared__ char smem[];
    const int tid  = threadIdx.x;
    const int wid  = tid >> 5;
    const int lane = tid & 31;
    const int gq   = lane >> 2;
    const int q2   = 2 * (lane & 3);
    const int zn   = gq & 4;
    const int rowg = wid & 1;
    const int colh = (wid >> 1) & 1;
    const int outs = wid >> 2;

    // resident weight images + b1
    {
        const float4* sa = (const float4*)g_Wa;
        const float4* sb = (const float4*)g_Wb;
        float4* da = (float4*)(smem + G0_WA);
        float4* db = (float4*)(smem + G0_WB);
        #pragma unroll
        for (int i = 0; i < 16; i++) {
            da[tid + i * 256] = sa[tid + i * 256];
            db[tid + i * 256] = sb[tid + i * 256];
        }
        ((float*)(smem + G0_B1))[tid] = b1[tid];
    }
    __syncthreads();

    float2 b1v[16];
    #pragma unroll
    for (int nt = 0; nt < 16; nt++)
        b1v[nt] = *(const float2*)((float*)(smem + G0_B1) +
                                   128 * colh + 8 * nt + 2 * (lane & 3));

    const int rbase = 32 * rowg + gq;
    const int e   = tid >> 2;     // local row 0..63
    const int sub = tid & 3;      // plane pair selector
    uint32_t* Axw = (uint32_t*)(smem + G0_A);
    const uint32_t* Wim = (const uint32_t*)(smem + (outs ? G0_WB : G0_WA));

    for (int tile = blockIdx.x; tile < N_TILES0; tile += GRID_MAIN) {
        const int grow = tile * 64 + e;
        const bool gok = grow < NN_NODES;
        __syncthreads();
        // stage x rows: planes 2sub, 2sub+1 (16 floats each)
        #pragma unroll
        for (int pi = 0; pi < 2; pi++) {
            const int p = 2 * sub + pi;
            float4 v[4];
            const float* sp = x + (size_t)grow * 128 + p * 16;
            #pragma unroll
            for (int j = 0; j < 4; j++)
                v[j] = gok ? *(const float4*)(sp + j * 4) : make_float4(0, 0, 0, 0);
            stage_row(Axw, e, p, 512, v);
        }
        __syncthreads();

        float acc[2][16][4];
        #pragma unroll
        for (int mt = 0; mt < 2; mt++)
            #pragma unroll
            for (int nt = 0; nt < 16; nt++) {
                float bx = outs ? 0.f : b1v[nt].x;
                float by = outs ? 0.f : b1v[nt].y;
                acc[mt][nt][0] = bx; acc[mt][nt][1] = by;
                acc[mt][nt][2] = bx; acc[mt][nt][3] = by;
            }

        #pragma unroll
        for (int ks = 0; ks < 8; ks++) {
            const uint32_t* Aks = Axw + ks * 512;
            const uint32_t* Bks = Wim + ks * 2048;
            const int qz = q2 ^ zn ^ ((ks & 1) << 1);
            uint32_t af[2][4];
            #pragma unroll
            for (int mt = 0; mt < 2; mt++) {
                const int r0 = rbase + 16 * mt;
                uint2 lo = *(const uint2*)&Aks[r0 * 8 + qz];
                uint2 hi = *(const uint2*)&Aks[(r0 + 8) * 8 + qz];
                af[mt][0] = lo.x; af[mt][1] = hi.x;
                af[mt][2] = lo.y; af[mt][3] = hi.y;
            }
            #pragma unroll
            for (int nt = 0; nt < 16; nt++) {
                const int n = 128 * colh + 8 * nt + gq;
                uint2 bv = *(const uint2*)&Bks[n * 8 + qz];
                #pragma unroll
                for (int mt = 0; mt < 2; mt++) mma16(acc[mt][nt], af[mt], bv.x, bv.y);
            }
        }

        __half* outp = outs ? g_v : g_u;
        #pragma unroll
        for (int mt = 0; mt < 2; mt++) {
            const int r0 = tile * 64 + rbase + 16 * mt;
            #pragma unroll
            for (int nt = 0; nt < 16; nt++) {
                const int cn = 128 * colh + 8 * nt + 2 * (lane & 3);
                if (r0 < NN_NODES)
                    *(uint32_t*)(outp + (size_t)r0 * 256 + cn) =
                        f2h2(acc[mt][nt][0], acc[mt][nt][1]);
                if (r0 + 8 < NN_NODES)
                    *(uint32_t*)(outp + (size_t)(r0 + 8) * 256 + cn) =
                        f2h2(acc[mt][nt][2], acc[mt][nt][3]);
            }
        }
    }
}

// ============================================================================
// g1: per edge-tile: acc = ea@W1c; h = relu(acc + u[row] + v[col]);
//     hsum[row] += h; degf[row] += 1.
// uv staging: row stride 136 words, halves at +0/+68, word XOR (row&4).
// ============================================================================
__global__ void __launch_bounds__(256, 1)
edgeconv_g1(const void* __restrict__ ei, const float* __restrict__ ea) {
    extern __shared__ char smem[];
    const int tid  = threadIdx.x;
    const int wid  = tid >> 5;
    const int lane = tid & 31;
    const int gq   = lane >> 2;
    const int q2   = 2 * (lane & 3);
    const int zn   = gq & 4;
    const int wr   = wid >> 2;   // rows [64wr, +64)
    const int wc   = wid & 3;    // cols [64wc, +64)
    const int is64 = g_is64;

    int* rows_s = (int*)(smem + G1_ROWS);
    int* cols_s = (int*)(smem + G1_COLS);
    uint32_t* WC  = (uint32_t*)(smem + G1_WC);
    uint32_t* AEA = (uint32_t*)(smem + G1_AEA);
    uint32_t* UV  = (uint32_t*)(smem + G1_UV);

    {   // resident W1c image (32 KB)
        const float4* src = (const float4*)g_Wc;
        float4* dst = (float4*)(smem + G1_WC);
        #pragma unroll
        for (int i = 0; i < 8; i++) dst[tid + i * 256] = src[tid + i * 256];
    }

    const int rbase = 64 * wr + gq;
    const int e  = tid >> 1;
    const int h  = tid & 1;
    const int e2 = (e >> 2) & 1;           // (e&4)>>2
    const int hh68 = 68 * (wc >> 1);
    const int wbase = 32 * (wc & 1) + (lane & 3);
    const int g4 = gq & 4;

    for (int tile = blockIdx.x; tile < N_TILES; tile += GRID_MAIN) {
        const int ebase = tile * TILE_E;
        __syncthreads();   // prior tile epilogue done with UV / indices
        if (tid < 128) {
            if (is64) {
                rows_s[tid] = (int)((const long long*)ei)[ebase + tid];
                cols_s[tid] = (int)((const long long*)ei)[E_TOTAL + ebase + tid];
            } else {
                rows_s[tid] = ((const int*)ei)[ebase + tid];
                cols_s[tid] = ((const int*)ei)[E_TOTAL + ebase + tid];
            }
        }
        __syncthreads();

        // stage ea chunk: thread (e,h) -> planes 2h, 2h+1 (16 f32 each)
        #pragma unroll
        for (int pi = 0; pi < 2; pi++) {
            const int p = 2 * h + pi;
            float4 v[4];
            const float* sp = ea + (size_t)(ebase + e) * 64 + p * 16;
            #pragma unroll
            for (int j = 0; j < 4; j++) v[j] = *(const float4*)(sp + j * 4);
            stage_row(AEA, e, p, 1024, v);
        }
        // stage uv = u[row]+v[col] (fp16): 16 groups of 16 B per thread
        {
            const __half* up = g_u + (size_t)rows_s[e] * 256;
            const __half* vp = g_v + (size_t)cols_s[e] * 256;
            uint32_t* uvrow = UV + e * 136 + 68 * h;
            #pragma unroll
            for (int j = 0; j < 16; j++) {
                const int lg = 16 * h + (j ^ e2);
                uint4 a = *(const uint4*)(up + lg * 8);
                uint4 b = *(const uint4*)(vp + lg * 8);
                uint4 r;
                r.x = hadd2u(a.x, b.x); r.y = hadd2u(a.y, b.y);
                r.z = hadd2u(a.z, b.z); r.w = hadd2u(a.w, b.w);
                *(uint4*)(uvrow + 4 * j) = r;
            }
        }
        __syncthreads();

        // ea GEMM: K=64 -> 4 k16 planes
        float acc[4][8][4];
        #pragma unroll
        for (int mt = 0; mt < 4; mt++)
            #pragma unroll
            for (int nt = 0; nt < 8; nt++)
                #pragma unroll
                for (int i = 0; i < 4; i++) acc[mt][nt][i] = 0.f;

        #pragma unroll
        for (int ks = 0; ks < 4; ks++) {
            const uint32_t* Aks = AEA + ks * 1024;
            const uint32_t* Bks = WC + ks * 2048;
            const int qz = q2 ^ zn ^ ((ks & 1) << 1);
            uint32_t af[4][4];
            #pragma unroll
            for (int mt = 0; mt < 4; mt++) {
                const int r0 = rbase + 16 * mt;
                uint2 lo = *(const uint2*)&Aks[r0 * 8 + qz];
                uint2 hi = *(const uint2*)&Aks[(r0 + 8) * 8 + qz];
                af[mt][0] = lo.x; af[mt][1] = hi.x;
                af[mt][2] = lo.y; af[mt][3] = hi.y;
            }
            #pragma unroll
            for (int nt = 0; nt < 8; nt++) {
                const int n = 64 * wc + 8 * nt + gq;
                uint2 bv = *(const uint2*)&Bks[n * 8 + qz];
                #pragma unroll
                for (int mt = 0; mt < 4; mt++) mma16(acc[mt][nt], af[mt], bv.x, bv.y);
            }
        }

        // epilogue: h = relu(acc + uv); scatter
        #pragma unroll
        for (int mt = 0; mt < 4; mt++) {
            const int r0 = rbase + 16 * mt;
            const uint32_t* uv0 = UV + r0 * 136 + hh68;
            const uint32_t* uv1 = UV + (r0 + 8) * 136 + hh68;
            float* hs0 = g_hsum + (size_t)rows_s[r0] * 256;
            float* hs1 = g_hsum + (size_t)rows_s[r0 + 8] * 256;
            #pragma unroll
            for (int nt = 0; nt < 8; nt++) {
                const int off = (wbase + 4 * nt) ^ g4;
                const int cn  = 64 * wc + 8 * nt + 2 * (lane & 3);
                float2 f0 = __half22float2(*(const __half2*)&uv0[off]);
                float2 f1 = __half22float2(*(const __half2*)&uv1[off]);
                red2(hs0 + cn, fmaxf(acc[mt][nt][0] + f0.x, 0.f),
                               fmaxf(acc[mt][nt][1] + f0.y, 0.f));
                red2(hs1 + cn, fmaxf(acc[mt][nt][2] + f1.x, 0.f),
                               fmaxf(acc[mt][nt][3] + f1.y, 0.f));
            }
            if (wc == 0 && (lane & 3) == 0) {
                red1(g_degf + rows_s[r0], 1.0f);
                red1(g_degf + rows_s[r0 + 8], 1.0f);
            }
        }
    }
}

// ============================================================================
// g2: out[n,:] = fp16(hsum[n]) @ W2 + degf[n]*b2  (dense 100k x 256 x 128)
// ============================================================================
__global__ void __launch_bounds__(256, 1)
edgeconv_g2(const float* __restrict__ b2, float* __restrict__ out) {
    extern __shared__ char smem[];
    const int tid  = threadIdx.x;
    const int wid  = tid >> 5;
    const int lane = tid & 31;
    const int wr   = wid >> 1;
    const int wc   = wid & 1;
    const int gq   = lane >> 2;
    const int q2   = 2 * (lane & 3);
    const int zn   = gq & 4;

    float* sB2 = (float*)(smem + F_B2_OFF);
    if (tid < 128) sB2[tid] = b2[tid];
    {
        const float4* src = (const float4*)g_W2h;
        float4* dst = (float4*)(smem + F_W2_OFF);
        #pragma unroll
        for (int i = 0; i < 16; i++) dst[tid + i * 256] = src[tid + i * 256];
    }
    __syncthreads();

    float2 b2v[8];
    #pragma unroll
    for (int nt = 0; nt < 8; nt++)
        b2v[nt] = *(const float2*)&sB2[64 * wc + 8 * nt + 2 * (lane & 3)];

    const int rbase = 32 * wr + gq;
    const int e     = tid >> 1;
    const int half  = tid & 1;

    for (int tile = blockIdx.x; tile < N_TILES2; tile += GRID_MAIN) {
        const int rg = tile * 128 + e;
        const bool ok = rg < NN_NODES;
        float4 v[4];
        {
            const float* p = g_hsum + (size_t)rg * 256 + half * 16;
            #pragma unroll
            for (int j = 0; j < 4; j++)
                v[j] = ok ? *(const float4*)(p + j * 4) : make_float4(0, 0, 0, 0);
            stage_row((uint32_t*)(smem + F_ABUF_OFF), e, half, 1024, v);
            p = g_hsum + (size_t)rg * 256 + 32 + half * 16;
            #pragma unroll
            for (int j = 0; j < 4; j++)
                v[j] = ok ? *(const float4*)(p + j * 4) : make_float4(0, 0, 0, 0);
        }
        __syncthreads();

        float acc[2][8][4];
        #pragma unroll
        for (int mt = 0; mt < 2; mt++)
            #pragma unroll
            for (int nt = 0; nt < 8; nt++)
                #pragma unroll
                for (int i = 0; i < 4; i++) acc[mt][nt][i] = 0.f;

        #pragma unroll 1
        for (int j = 0; j < 8; j++) {
            const int s = j & 1;
            const uint32_t* A16 = (const uint32_t*)(smem + F_ABUF_OFF + s * 8192);
            const uint32_t* B16 = (const uint32_t*)(smem + F_W2_OFF + j * 8192);
            #pragma unroll
            for (int ks = 0; ks < 2; ks++) {
                const uint32_t* Aks = A16 + ks * 1024;
                const uint32_t* Bks = B16 + ks * 1024;
                const int qz = q2 ^ zn ^ (ks << 1);
                uint32_t af[2][4];
                #pragma unroll
                for (int mt = 0; mt < 2; mt++) {
                    const int r0 = rbase + 16 * mt;
                    uint2 lo = *(const uint2*)&Aks[r0 * 8 + qz];
                    uint2 hi = *(const uint2*)&Aks[(r0 + 8) * 8 + qz];
                    af[mt][0] = lo.x; af[mt][1] = hi.x;
                    af[mt][2] = lo.y; af[mt][3] = hi.y;
                }
                #pragma unroll
                for (int nt = 0; nt < 8; nt++) {
                    const int n = 64 * wc + 8 * nt + gq;
                    uint2 bv = *(const uint2*)&Bks[n * 8 + qz];
                    #pragma unroll
                    for (int mt = 0; mt < 2; mt++) mma16(acc[mt][nt], af[mt], bv.x, bv.y);
                }
            }
            if (j < 7) {
                stage_row((uint32_t*)(smem + F_ABUF_OFF + (s ^ 1) * 8192), e, half, 1024, v);
                if (j < 6) {
                    const float* p = g_hsum + (size_t)rg * 256 + (j + 2) * 32 + half * 16;
                    #pragma unroll
                    for (int jj = 0; jj < 4; jj++)
                        v[jj] = ok ? *(const float4*)(p + jj * 4) : make_float4(0, 0, 0, 0);
                }
            }
            __syncthreads();
        }

        #pragma unroll
        for (int mt = 0; mt < 2; mt++) {
            const int r0 = tile * 128 + rbase + 16 * mt;
            const bool ok0 = r0 < NN_NODES;
            const bool ok1 = (r0 + 8) < NN_NODES;
            const float dg0 = ok0 ? g_degf[r0] : 0.f;
            const float dg1 = ok1 ? g_degf[r0 + 8] : 0.f;
            #pragma unroll
            for (int nt = 0; nt < 8; nt++) {
                const int cn = 64 * wc + 8 * nt + 2 * (lane & 3);
                if (ok0) {
                    float2 o = make_float2(acc[mt][nt][0] + dg0 * b2v[nt].x,
                                           acc[mt][nt][1] + dg0 * b2v[nt].y);
                    *(float2*)(out + (size_t)r0 * 128 + cn) = o;
                }
                if (ok1) {
                    float2 o = make_float2(acc[mt][nt][2] + dg1 * b2v[nt].x,
                                           acc[mt][nt][3] + dg1 * b2v[nt].y);
                    *(float2*)(out + (size_t)(r0 + 8) * 128 + cn) = o;
                }
            }
        }
    }
}

// ============================================================================
// Launch
// ============================================================================
extern "C" void kernel_launch(void* const* d_in, const int* in_sizes, int n_in,
                              void* d_out, int out_size) {
    const float* x  = (const float*)d_in[0];
    const void*  ei = d_in[1];
    const float* ea = (const float*)d_in[2];
    const float* W1 = (const float*)d_in[3];
    const float* b1 = (const float*)d_in[4];
    const float* W2 = (const float*)d_in[5];
    const float* b2 = (const float*)d_in[6];
    float* out = (float*)d_out;

    cudaFuncSetAttribute(edgeconv_g0,
                         cudaFuncAttributeMaxDynamicSharedMemorySize, SMEM_G0);
    cudaFuncSetAttribute(edgeconv_g1,
                         cudaFuncAttributeMaxDynamicSharedMemorySize, SMEM_G1);
    cudaFuncSetAttribute(edgeconv_g2,
                         cudaFuncAttributeMaxDynamicSharedMemorySize, SMEM_FIN);

    setup_kernel<<<SETUP_BLOCKS, 256>>>(ei, W1, W2);
    edgeconv_g0<<<GRID_MAIN, 256, SMEM_G0>>>(x, b1);
    edgeconv_g1<<<GRID_MAIN, 256, SMEM_G1>>>(ei, ea);
    edgeconv_g2<<<GRID_MAIN, 256, SMEM_FIN>>>(b2, out);
}